// round 2
// baseline (speedup 1.0000x reference)
#include <cuda_runtime.h>
#include <math.h>

// Problem constants
#define TTOK   32768      // B*S
#define SEQ    8192
#define NB     4
#define DIM    512
#define HDIM   64

// ---------------- scratch (__device__ globals; no allocation allowed) -------
__device__ float  g_xn[(size_t)TTOK * DIM];     // rmsnorm(x); later reused for Y
__device__ float  g_qkv[(size_t)TTOK * 1024];   // [Q(512) | K(256) | V(256)] per token
__device__ float2 g_rope[SEQ * 32];             // (cos, sin) per (s, j)
__device__ float  g_pkv[64 * 16 * 64];          // partial KV  [chunk][b*4+hkv][d]
__device__ float  g_pks[64 * 16 * 64];          // partial Ksum
__device__ float  g_kv[16 * 64];                // KV    [b*4+hkv][d]
__device__ float  g_ks[16 * 64];                // K_sum [b*4+hkv][d]

// ---------------- f32x2 packed-FMA helpers ----------------------------------
__device__ __forceinline__ unsigned long long pack_dup(float a) {
    unsigned long long r;
    asm("mov.b64 %0, {%1, %1};" : "=l"(r) : "f"(a));
    return r;
}
__device__ __forceinline__ void fma2(unsigned long long& d,
                                     unsigned long long a,
                                     unsigned long long b) {
    asm("fma.rn.f32x2 %0, %1, %2, %0;" : "+l"(d) : "l"(a), "l"(b));
}

// ---------------- RoPE table -------------------------------------------------
// Reference: inv = 1/theta^(j/32) (fp32), ang = fp32(s * inv), cos/sin in fp32.
// We compute inv/cos/sin via double of the fp32-rounded angle for accuracy.
__global__ void rope_table_kernel() {
    int idx = blockIdx.x * blockDim.x + threadIdx.x;
    if (idx >= SEQ * 32) return;
    int s = idx >> 5;
    int j = idx & 31;
    float inv = (float)(1.0 / pow(10000.0, (double)j / 32.0));
    float ang = (float)s * inv;            // fp32 rounding matches reference
    double a = (double)ang;
    g_rope[idx] = make_float2((float)cos(a), (float)sin(a));
}

// ---------------- RMSNorm ----------------------------------------------------
__global__ void rmsnorm_kernel(const float* __restrict__ x,
                               const float* __restrict__ w) {
    int t = blockIdx.x;
    int tid = threadIdx.x;                 // 128 threads, 1 float4 each
    const float4 v = ((const float4*)(x + (size_t)t * DIM))[tid];
    float ss = v.x * v.x + v.y * v.y + v.z * v.z + v.w * v.w;
    #pragma unroll
    for (int off = 16; off > 0; off >>= 1)
        ss += __shfl_xor_sync(0xffffffffu, ss, off);
    __shared__ float sm[4];
    if ((tid & 31) == 0) sm[tid >> 5] = ss;
    __syncthreads();
    float tot = sm[0] + sm[1] + sm[2] + sm[3];
    float r = rsqrtf(tot * (1.0f / DIM) + 1e-6f);
    const float4 wv = ((const float4*)w)[tid];
    float4 o = make_float4(v.x * r * wv.x, v.y * r * wv.y,
                           v.z * r * wv.z, v.w * r * wv.w);
    ((float4*)(g_xn + (size_t)t * DIM))[tid] = o;
}

// ---------------- SGEMM: C[M,N] = A[M,512] * W[N,512]^T ----------------------
// 128x128x16 tiles, 256 threads, 8x8 per thread, packed f32x2 accumulation.
// mode: Cout == nullptr -> C = g_qkv (ldc=1024, N=1024, B rows split q/k/v)
//       Cout != nullptr -> C = Cout  (ldc=512,  N=512,  B = B0 only)
__global__ __launch_bounds__(256, 2)
void gemm_kernel(const float* __restrict__ B0,
                 const float* __restrict__ B1,
                 const float* __restrict__ B2,
                 float* __restrict__ Cout) {
    const int K = 512;
    __shared__ float As[16][128];
    __shared__ float Bs[16][128];

    const float* A = g_xn;
    float* C;
    int ldc;
    if (Cout) { C = Cout; ldc = 512; } else { C = g_qkv; ldc = 1024; }

    int m0 = blockIdx.x * 128;
    int nb = blockIdx.y * 128;
    const float* Bbase;
    int nOff;
    if (nb < 512)      { Bbase = B0; nOff = nb; }
    else if (nb < 768) { Bbase = B1; nOff = nb - 512; }
    else               { Bbase = B2; nOff = nb - 768; }

    int tid = threadIdx.x;
    int lr = tid >> 2;            // 0..63
    int lc = (tid & 3) * 4;       // 0,4,8,12
    int ty = tid >> 4;            // 0..15
    int tx = tid & 15;            // 0..15

    const float* Aptr = A + (size_t)(m0 + lr) * K + lc;
    const float* Bptr = Bbase + (size_t)(nOff + lr) * K + lc;

    float4 pa0 = *(const float4*)(Aptr);
    float4 pa1 = *(const float4*)(Aptr + 64 * K);
    float4 pb0 = *(const float4*)(Bptr);
    float4 pb1 = *(const float4*)(Bptr + 64 * K);

    unsigned long long acc[8][4];
    #pragma unroll
    for (int i = 0; i < 8; ++i)
        #pragma unroll
        for (int j = 0; j < 4; ++j) acc[i][j] = 0ull;

    #pragma unroll 1
    for (int kt = 0; kt < 32; ++kt) {
        As[lc + 0][lr] = pa0.x; As[lc + 1][lr] = pa0.y;
        As[lc + 2][lr] = pa0.z; As[lc + 3][lr] = pa0.w;
        As[lc + 0][lr + 64] = pa1.x; As[lc + 1][lr + 64] = pa1.y;
        As[lc + 2][lr + 64] = pa1.z; As[lc + 3][lr + 64] = pa1.w;
        Bs[lc + 0][lr] = pb0.x; Bs[lc + 1][lr] = pb0.y;
        Bs[lc + 2][lr] = pb0.z; Bs[lc + 3][lr] = pb0.w;
        Bs[lc + 0][lr + 64] = pb1.x; Bs[lc + 1][lr + 64] = pb1.y;
        Bs[lc + 2][lr + 64] = pb1.z; Bs[lc + 3][lr + 64] = pb1.w;
        __syncthreads();

        if (kt < 31) {
            pa0 = *(const float4*)(Aptr + (kt + 1) * 16);
            pa1 = *(const float4*)(Aptr + 64 * K + (kt + 1) * 16);
            pb0 = *(const float4*)(Bptr + (kt + 1) * 16);
            pb1 = *(const float4*)(Bptr + 64 * K + (kt + 1) * 16);
        }

        #pragma unroll
        for (int k = 0; k < 16; ++k) {
            float4 av0 = *(const float4*)&As[k][ty * 8];
            float4 av1 = *(const float4*)&As[k][ty * 8 + 4];
            double2 bq0 = *(const double2*)&Bs[k][tx * 8];
            double2 bq1 = *(const double2*)&Bs[k][tx * 8 + 4];
            unsigned long long b0 = __double_as_longlong(bq0.x);
            unsigned long long b1 = __double_as_longlong(bq0.y);
            unsigned long long b2 = __double_as_longlong(bq1.x);
            unsigned long long b3 = __double_as_longlong(bq1.y);
            float a_[8] = {av0.x, av0.y, av0.z, av0.w,
                           av1.x, av1.y, av1.z, av1.w};
            #pragma unroll
            for (int i = 0; i < 8; ++i) {
                unsigned long long ap = pack_dup(a_[i]);
                fma2(acc[i][0], ap, b0);
                fma2(acc[i][1], ap, b1);
                fma2(acc[i][2], ap, b2);
                fma2(acc[i][3], ap, b3);
            }
        }
        __syncthreads();
    }

    int row0 = m0 + ty * 8;
    int col = nb + tx * 8;
    #pragma unroll
    for (int i = 0; i < 8; ++i) {
        double2 r0, r1;
        r0.x = __longlong_as_double(acc[i][0]);
        r0.y = __longlong_as_double(acc[i][1]);
        r1.x = __longlong_as_double(acc[i][2]);
        r1.y = __longlong_as_double(acc[i][3]);
        *(double2*)&C[(size_t)(row0 + i) * ldc + col] = r0;
        *(double2*)&C[(size_t)(row0 + i) * ldc + col + 4] = r1;
    }
}

// ---------------- K reduction: KV[d] = sum_s phi(rope(k))*v ; Ksum ----------
__global__ void kv_reduce_kernel() {
    int bh = blockIdx.y;          // 0..15 = b*4 + hkv
    int b = bh >> 2, hkv = bh & 3;
    int chunk = blockIdx.x;       // 0..63, 128 s-positions each
    int tid = threadIdx.x;        // 256
    int d = tid & 63;
    int si = tid >> 6;            // 0..3
    int j = d >> 1;
    int odd = d & 1;

    float akv = 0.f, aks = 0.f;
    int s0 = chunk * 128;
    for (int i = 0; i < 32; ++i) {
        int s = s0 + si + i * 4;
        const float* row = g_qkv + (size_t)(b * SEQ + s) * 1024;
        float k = row[512 + hkv * 64 + d];
        float kp = __shfl_xor_sync(0xffffffffu, k, 1);  // pair partner (d^1)
        float2 cs = g_rope[s * 32 + j];
        float kr = odd ? (kp * cs.y + k * cs.x) : (k * cs.x - kp * cs.y);
        float kl = kr > 0.f ? kr + 1.f : expf(kr);       // elu(x)+1
        float v = row[768 + hkv * 64 + d];
        akv += kl * v;
        aks += kl;
    }
    __shared__ float skv[4][64];
    __shared__ float sks[4][64];
    skv[si][d] = akv;
    sks[si][d] = aks;
    __syncthreads();
    if (tid < 64) {
        float KV = skv[0][tid] + skv[1][tid] + skv[2][tid] + skv[3][tid];
        float KS = sks[0][tid] + sks[1][tid] + sks[2][tid] + sks[3][tid];
        g_pkv[(chunk * 16 + bh) * 64 + tid] = KV;
        g_pks[(chunk * 16 + bh) * 64 + tid] = KS;
    }
}

__global__ void kv_final_kernel() {
    int bh = blockIdx.x;          // 16
    int d = threadIdx.x;          // 64
    float a = 0.f, c = 0.f;
    for (int ch = 0; ch < 64; ++ch) {
        a += g_pkv[(ch * 16 + bh) * 64 + d];
        c += g_pks[(ch * 16 + bh) * 64 + d];
    }
    g_kv[bh * 64 + d] = a;
    g_ks[bh * 64 + d] = c;
}

// ---------------- Q path: rope, phi, Z, Y (written into g_xn) ---------------
__global__ void qy_kernel() {
    int t = blockIdx.x;
    int b = t >> 13;
    int spos = t & (SEQ - 1);
    int tid = threadIdx.x;        // 512
    int h = tid >> 6;
    int d = tid & 63;
    int hkv = h >> 1;

    float q = g_qkv[(size_t)t * 1024 + h * 64 + d];
    float qp = __shfl_xor_sync(0xffffffffu, q, 1);
    float2 cs = g_rope[spos * 32 + (d >> 1)];
    float qr = (d & 1) ? (qp * cs.y + q * cs.x) : (q * cs.x - qp * cs.y);
    float ql = qr > 0.f ? qr + 1.f : expf(qr);

    float z = ql * g_ks[(b * 4 + hkv) * 64 + d];
    #pragma unroll
    for (int off = 16; off > 0; off >>= 1)
        z += __shfl_xor_sync(0xffffffffu, z, off);
    __shared__ float zs[16];
    if ((tid & 31) == 0) zs[tid >> 5] = z;
    __syncthreads();
    float Z = zs[h * 2] + zs[h * 2 + 1];

    float y = ql * g_kv[(b * 4 + hkv) * 64 + d] / (Z + 1e-6f);
    g_xn[(size_t)t * DIM + h * 64 + d] = y;   // reuse g_xn as Y buffer
}

// ---------------- launch -----------------------------------------------------
extern "C" void kernel_launch(void* const* d_in, const int* in_sizes, int n_in,
                              void* d_out, int out_size) {
    const float* x  = (const float*)d_in[0];
    const float* nw = (const float*)d_in[1];
    const float* wq = (const float*)d_in[2];
    const float* wk = (const float*)d_in[3];
    const float* wv = (const float*)d_in[4];
    const float* wo = (const float*)d_in[5];
    float* out = (float*)d_out;

    rope_table_kernel<<<(SEQ * 32 + 255) / 256, 256>>>();
    rmsnorm_kernel<<<TTOK, 128>>>(x, nw);
    gemm_kernel<<<dim3(TTOK / 128, 8), 256>>>(wq, wk, wv, nullptr);   // QKV
    kv_reduce_kernel<<<dim3(64, 16), 256>>>();
    kv_final_kernel<<<16, 64>>>();
    qy_kernel<<<TTOK, 512>>>();
    gemm_kernel<<<dim3(TTOK / 128, 4), 256>>>(wo, wo, wo, out);       // out proj
}